// round 12
// baseline (speedup 1.0000x reference)
#include <cuda_runtime.h>
#include <math.h>

// Problem constants (fixed by the reference)
#define POOL   100
#define NTASKS 10
#define NB_PT  (POOL / NTASKS)       // 10
#define PLEN   8
#define EMBD   768
#define BATCH  512
#define ED4    (EMBD / 4)            // 192

#define A_BLOCKS    BATCH            // 512 — single wave, grid barrier safe
#define PMT_BLOCKS  BATCH            // mega: pmt first
#define COPY_BLOCKS 2560             // mega: copy after

// Scratch (allocation-free; zero-init at load, counters reset each launch)
__device__ float    g_sim[BATCH * POOL];
__device__ float    g_w1[POOL * EMBD];  // e^2 * diag
__device__ float    g_w2[POOL * EMBD];  // e^2 * diag^2
__device__ float    g_w3[POOL * EMBD];  // e^2
__device__ unsigned g_bar1;             // wvec arrive counter
__device__ unsigned g_bar2;             // completion counter (for reset)

// ---------------------------------------------------------------------------
// Kernel A: wvec (all blocks cooperate) -> grid barrier -> sim (block per b).
// 512 blocks x 256 threads = single wave on 148 SMs (27.7 warps/SM).
// ---------------------------------------------------------------------------
__global__ void __launch_bounds__(256) simprep_kernel(
        const float* __restrict__ x_querry,
        const float* __restrict__ e_a,
        const float* __restrict__ e_p,
        const int*   __restrict__ task_id_p) {
    const int tid  = threadIdx.x;
    const int warp = tid >> 5;
    const int lane = tid & 31;

    // ---- phase 1: w vectors, one float4 task per thread (19200 tasks) ----
    {
        int i = blockIdx.x * 256 + tid;
        if (i < POOL * ED4) {
            const float4* ep4 = (const float4*)e_p;
            int k  = i / ED4;
            int d4 = i % ED4;
            float4 g = make_float4(0.f, 0.f, 0.f, 0.f);
#pragma unroll
            for (int l = 0; l < PLEN; l++) {
                float4 v = ep4[((size_t)k * PLEN + l) * ED4 + d4];
                g.x += v.x * v.x; g.y += v.y * v.y;
                g.z += v.z * v.z; g.w += v.w * v.w;
            }
            float4 e = ((const float4*)e_a)[i];
            float4 e2 = make_float4(e.x * e.x, e.y * e.y, e.z * e.z, e.w * e.w);
            float4 w1 = make_float4(e2.x * g.x, e2.y * g.y, e2.z * g.z, e2.w * g.w);
            float4 w2 = make_float4(w1.x * g.x, w1.y * g.y, w1.z * g.z, w1.w * g.w);
            ((float4*)g_w3)[i] = e2;
            ((float4*)g_w1)[i] = w1;
            ((float4*)g_w2)[i] = w2;
        }
    }

    // ---- grid barrier (single-wave guaranteed; replay-safe reset below) ----
    __threadfence();
    __syncthreads();
    if (tid == 0) {
        atomicAdd(&g_bar1, 1u);
        while (atomicAdd(&g_bar1, 0u) < A_BLOCKS) __nanosleep(32);
    }
    __syncthreads();
    __threadfence();

    // ---- phase 2: sims for b = blockIdx.x ----
    const int task_end = (*task_id_p + 1) * NB_PT;
    const int b = blockIdx.x;

    const float4* w14 = (const float4*)g_w1;
    const float4* w24 = (const float4*)g_w2;
    const float4* w34 = (const float4*)g_w3;

    for (int k = warp; k < task_end; k += 8) {
        const int row = POOL - task_end + k;
        const float4* xq4 = (const float4*)(x_querry +
                            ((size_t)b * POOL + row) * EMBD);
        const size_t kb = (size_t)k * ED4;

        float s1 = 0.f, s2 = 0.f, s3 = 0.f;
#pragma unroll
        for (int j = 0; j < ED4 / 32; j++) {   // 6 iterations
            int idx = lane + j * 32;
            float4 x  = xq4[idx];
            float4 a1 = w14[kb + idx];
            float4 a2 = w24[kb + idx];
            float4 a3 = w34[kb + idx];
            float xx;
            xx = x.x * x.x; s1 += xx * a1.x; s2 += xx * a2.x; s3 += xx * a3.x;
            xx = x.y * x.y; s1 += xx * a1.y; s2 += xx * a2.y; s3 += xx * a3.y;
            xx = x.z * x.z; s1 += xx * a1.z; s2 += xx * a2.z; s3 += xx * a3.z;
            xx = x.w * x.w; s1 += xx * a1.w; s2 += xx * a2.w; s3 += xx * a3.w;
        }
#pragma unroll
        for (int o = 16; o > 0; o >>= 1) {
            s1 += __shfl_down_sync(0xFFFFFFFFu, s1, o);
            s2 += __shfl_down_sync(0xFFFFFFFFu, s2, o);
            s3 += __shfl_down_sync(0xFFFFFFFFu, s3, o);
        }
        if (lane == 0) {
            const float eps = 1e-12f;
            float n1 = fmaxf(sqrtf(s2), eps);
            float n2 = fmaxf(sqrtf(s3), eps);
            g_sim[(size_t)b * POOL + k] = s1 / (n1 * n2);
        }
    }

    // ---- replay-safe reset: last block zeroes both counters ----
    __syncthreads();
    if (tid == 0) {
        unsigned t = atomicAdd(&g_bar2, 1u);
        if (t == A_BLOCKS - 1) {
            atomicExch(&g_bar2, 0u);
            atomicExch(&g_bar1, 0u);
        }
    }
}

// ---------------------------------------------------------------------------
// Kernel B: mega — round-2 proven config (95.7 us, regs 40):
//   blocks [0,512): pmt einsum; blocks [512, 3072): streaming copy.
// ---------------------------------------------------------------------------
__global__ void __launch_bounds__(256) mega_kernel(
        const float* __restrict__ e_p,
        const float* __restrict__ x_block,
        const int*   __restrict__ task_id_p,
        float* __restrict__ out,
        size_t xb_float4s) {
    if (blockIdx.x < PMT_BLOCKS) {
        // ---- einsum: int_pmt[b,l,d] = sum_k sim[b,k] * e_p[k,l,d] ----
        const int task_end = (*task_id_p + 1) * NB_PT;
        const int b = blockIdx.x;

        __shared__ float s_sim[POOL];
        if (threadIdx.x < POOL)
            s_sim[threadIdx.x] = g_sim[(size_t)b * POOL + threadIdx.x];
        __syncthreads();

        const float4* ep4 = (const float4*)e_p;
        const size_t KEY4 = (size_t)BATCH * (PLEN / 2) * ED4;

        for (int idx = threadIdx.x; idx < PLEN * ED4; idx += 256) {
            int l  = idx / ED4;
            int d4 = idx % ED4;
            float4 acc = make_float4(0.f, 0.f, 0.f, 0.f);
            for (int kk = 0; kk < task_end; kk++) {
                float s  = s_sim[kk];
                float4 v = ep4[((size_t)kk * PLEN + l) * ED4 + d4];
                acc.x += s * v.x; acc.y += s * v.y;
                acc.z += s * v.z; acc.w += s * v.w;
            }
            float4* o4;
            if (l < PLEN / 2)
                o4 = (float4*)out + ((size_t)b * (PLEN / 2) + l) * ED4 + d4;
            else
                o4 = (float4*)out + KEY4 +
                     ((size_t)b * (PLEN / 2) + (l - PLEN / 2)) * ED4 + d4;
            *o4 = acc;
        }
    } else {
        // ---- streaming copy: x_block -> out tail ----
        const float4* src = (const float4*)x_block;
        float4* dst = (float4*)(out + (size_t)BATCH * PLEN * EMBD);

        const size_t stride = (size_t)COPY_BLOCKS * 256;
        size_t i = (size_t)(blockIdx.x - PMT_BLOCKS) * 256 + threadIdx.x;

        for (; i + 3 * stride < xb_float4s; i += 4 * stride) {
            float4 v0 = __ldcs(src + i);
            float4 v1 = __ldcs(src + i + stride);
            float4 v2 = __ldcs(src + i + 2 * stride);
            float4 v3 = __ldcs(src + i + 3 * stride);
            __stcs(dst + i,              v0);
            __stcs(dst + i + stride,     v1);
            __stcs(dst + i + 2 * stride, v2);
            __stcs(dst + i + 3 * stride, v3);
        }
        for (; i < xb_float4s; i += stride)
            __stcs(dst + i, __ldcs(src + i));
    }
}

// ---------------------------------------------------------------------------
// Launch — two kernels: simprep (wvec+barrier+sim) -> mega (pmt+copy).
// Inputs (metadata order): x_querry, x_block, e_a, e_p, idx, task_id
// ---------------------------------------------------------------------------
extern "C" void kernel_launch(void* const* d_in, const int* in_sizes, int n_in,
                              void* d_out, int out_size) {
    const float* x_querry = (const float*)d_in[0];
    const float* x_block  = (const float*)d_in[1];
    const float* e_a      = (const float*)d_in[2];
    const float* e_p      = (const float*)d_in[3];
    const int*   task_id  = (const int*)d_in[5];
    float* out = (float*)d_out;

    simprep_kernel<<<A_BLOCKS, 256>>>(x_querry, e_a, e_p, task_id);

    size_t xb_float4s = (size_t)in_sizes[1] / 4;
    mega_kernel<<<PMT_BLOCKS + COPY_BLOCKS, 256>>>(
        e_p, x_block, task_id, out, xb_float4s);
}